// round 5
// baseline (speedup 1.0000x reference)
#include <cuda_runtime.h>
#include <cuda_bf16.h>
#include <math.h>

#define BB 4
#define SS 2048
#define DD 1024
#define HH 16
#define DP 64
#define MM (BB*SS)
#define NROWS (BB*HH*SS)       // 131072 attn rows
#define NTILES 16              // 2048/128 k-tiles per row

static const long long OUT_ELEMS  = (long long)BB*SS*DD;
static const long long ATTN_ELEMS = (long long)BB*HH*(long long)SS*SS;

// Scratch (__device__ globals per allocation rules)
__device__ float g_Qh[BB*HH*SS*DP];
__device__ float g_Kh[BB*HH*SS*DP];
__device__ float g_Vh[BB*HH*SS*DP];
__device__ float g_ctx[BB*SS*DD];
__device__ float g_attn[BB*HH*(long long)SS*SS];
__device__ float g_pm[(long long)NROWS*NTILES];   // partial max
__device__ float g_ps[(long long)NROWS*NTILES];   // partial sumexp
__device__ float g_rm[NROWS];                     // final row max
__device__ float g_rs[NROWS];                     // 1 / final row sum

// ---------------------------------------------------------------------------
__device__ __forceinline__ unsigned f2tf(float x) {
    unsigned r;
    asm("cvt.rna.tf32.f32 %0, %1;" : "=r"(r) : "f"(x));
    return r;
}

__device__ __forceinline__ void mma_tf32(float c[4], const unsigned a[4], const unsigned b[2]) {
    asm volatile(
        "mma.sync.aligned.m16n8k8.row.col.f32.tf32.tf32.f32 "
        "{%0,%1,%2,%3}, {%4,%5,%6,%7}, {%8,%9}, {%0,%1,%2,%3};"
        : "+f"(c[0]), "+f"(c[1]), "+f"(c[2]), "+f"(c[3])
        : "r"(a[0]), "r"(a[1]), "r"(a[2]), "r"(a[3]), "r"(b[0]), "r"(b[1]));
}

__device__ __forceinline__ void ldsm_x4(unsigned r[4], const unsigned* p) {
    unsigned addr = (unsigned)__cvta_generic_to_shared(p);
    asm volatile("ldmatrix.sync.aligned.m8n8.x4.shared.b16 {%0,%1,%2,%3}, [%4];"
                 : "=r"(r[0]), "=r"(r[1]), "=r"(r[2]), "=r"(r[3]) : "r"(addr));
}

// ---------------------------------------------------------------------------
// Generic TF32 GEMM for projections / output projection.
// ---------------------------------------------------------------------------
template<int BM, int BN, int BK, int WM, int WN, int SPLIT>
__global__ __launch_bounds__(256)
void mma_gemm_kernel(const float* __restrict__ A,
                     const float* __restrict__ Bm,
                     const float* __restrict__ bias,
                     float* __restrict__ C,
                     int M, int N, int K, float alpha)
{
    constexpr int AP = BK + 4;
    constexpr int BP = BN + 4;
    __shared__ unsigned As[BM * AP];
    __shared__ unsigned Bs[BK * BP];

    const int tid  = threadIdx.x;
    const int lane = tid & 31;
    const int warp = tid >> 5;
    constexpr int WN_CNT = BN / WN;
    const int wm = warp / WN_CNT;
    const int wn = warp % WN_CNT;
    const int row0 = blockIdx.y * BM;
    const int col0 = blockIdx.x * BN;

    constexpr int MT = WM / 16;
    constexpr int NT = WN / 8;
    float cfr[MT][NT][4];
#pragma unroll
    for (int mt = 0; mt < MT; mt++)
#pragma unroll
        for (int nt = 0; nt < NT; nt++)
#pragma unroll
            for (int i = 0; i < 4; i++) cfr[mt][nt][i] = 0.0f;

    for (int k0 = 0; k0 < K; k0 += BK) {
#pragma unroll
        for (int i = 0; i < (BM * BK / 4) / 256; i++) {
            int idx = tid + i * 256;
            int r   = idx / (BK / 4);
            int kq  = (idx % (BK / 4)) * 4;
            float4 v = *(const float4*)(A + (long long)(row0 + r) * K + k0 + kq);
            As[r * AP + kq + 0] = f2tf(v.x);
            As[r * AP + kq + 1] = f2tf(v.y);
            As[r * AP + kq + 2] = f2tf(v.z);
            As[r * AP + kq + 3] = f2tf(v.w);
        }
#pragma unroll
        for (int i = 0; i < (BK * BN / 4) / 256; i++) {
            int idx = tid + i * 256;
            int kk  = idx / (BN / 4);
            int nq  = (idx % (BN / 4)) * 4;
            float4 v = *(const float4*)(Bm + (long long)(k0 + kk) * N + col0 + nq);
            Bs[kk * BP + nq + 0] = f2tf(v.x);
            Bs[kk * BP + nq + 1] = f2tf(v.y);
            Bs[kk * BP + nq + 2] = f2tf(v.z);
            Bs[kk * BP + nq + 3] = f2tf(v.w);
        }
        __syncthreads();

#pragma unroll
        for (int ks = 0; ks < BK / 8; ks++) {
            unsigned af[MT][4];
            unsigned bf[NT][2];
            const int kb = ks * 8 + (lane & 3);
#pragma unroll
            for (int mt = 0; mt < MT; mt++) {
                int r = wm * WM + mt * 16 + (lane >> 2);
                af[mt][0] = As[r * AP + kb];
                af[mt][1] = As[(r + 8) * AP + kb];
                af[mt][2] = As[r * AP + kb + 4];
                af[mt][3] = As[(r + 8) * AP + kb + 4];
            }
#pragma unroll
            for (int nt = 0; nt < NT; nt++) {
                int cc = wn * WN + nt * 8 + (lane >> 2);
                bf[nt][0] = Bs[kb * BP + cc];
                bf[nt][1] = Bs[(kb + 4) * BP + cc];
            }
#pragma unroll
            for (int mt = 0; mt < MT; mt++)
#pragma unroll
                for (int nt = 0; nt < NT; nt++)
                    mma_tf32(cfr[mt][nt], af[mt], bf[nt]);
        }
        __syncthreads();
    }

#pragma unroll
    for (int mt = 0; mt < MT; mt++) {
#pragma unroll
        for (int nt = 0; nt < NT; nt++) {
#pragma unroll
            for (int i = 0; i < 4; i++) {
                int r = row0 + wm * WM + mt * 16 + (lane >> 2) + ((i >= 2) ? 8 : 0);
                int c = col0 + wn * WN + nt * 8 + (lane & 3) * 2 + (i & 1);
                float v = cfr[mt][nt][i] * alpha + (bias ? bias[c] : 0.0f);
                if (SPLIT == 0) {
                    C[(long long)r * N + c] = v;
                } else { // head-split store [b,h,s,d]
                    int b = r / SS, s = r % SS;
                    int h = c / DP, d = c % DP;
                    C[(((long long)b * HH + h) * SS + s) * DP + d] = v;
                }
            }
        }
    }
}

// ---------------------------------------------------------------------------
// K1: QK^T (K depth = 64, single smem stage) + mask + scale, writes raw
// masked logits + per-(row, 128-tile) partial softmax stats.
// Grid: (16 k-tiles, 16 q-tiles, 64 bh).  128x128 tile, 8 warps (2x4).
// ---------------------------------------------------------------------------
__global__ __launch_bounds__(256)
void qk_kernel(const float* __restrict__ mask, float* __restrict__ attn)
{
    extern __shared__ unsigned dynsm[];
    unsigned* Qs = dynsm;              // stride 68
    unsigned* Ks = dynsm + 128 * 68;   // stride 68, [n][k]
    float*    Cs = (float*)dynsm;      // stride 132 (reuse after compute)

    const int tid  = threadIdx.x;
    const int lane = tid & 31;
    const int warp = tid >> 5;
    const int wm = warp >> 2;          // 0..1
    const int wn = warp & 3;           // 0..3
    const int bh = blockIdx.z;
    const int q0 = blockIdx.y * 128;
    const int k0 = blockIdx.x * 128;

    const float* Qb = g_Qh + (long long)bh * SS * DP;
    const float* Kb = g_Kh + (long long)bh * SS * DP;

    // load Q tile [128 x 64] -> Qs[m][k], K tile -> Ks[n][k]
#pragma unroll
    for (int i = 0; i < 8; i++) {
        int idx = tid + i * 256;       // 0..2047
        int r   = idx >> 4;
        int c4  = (idx & 15) * 4;
        float4 v = *(const float4*)(Qb + (long long)(q0 + r) * DP + c4);
        Qs[r * 68 + c4 + 0] = f2tf(v.x);
        Qs[r * 68 + c4 + 1] = f2tf(v.y);
        Qs[r * 68 + c4 + 2] = f2tf(v.z);
        Qs[r * 68 + c4 + 3] = f2tf(v.w);
        float4 w = *(const float4*)(Kb + (long long)(k0 + r) * DP + c4);
        Ks[r * 68 + c4 + 0] = f2tf(w.x);
        Ks[r * 68 + c4 + 1] = f2tf(w.y);
        Ks[r * 68 + c4 + 2] = f2tf(w.z);
        Ks[r * 68 + c4 + 3] = f2tf(w.w);
    }
    __syncthreads();

    float acc[4][4][4];
#pragma unroll
    for (int mt = 0; mt < 4; mt++)
#pragma unroll
        for (int nt = 0; nt < 4; nt++)
#pragma unroll
            for (int i = 0; i < 4; i++) acc[mt][nt][i] = 0.0f;

    const int grp = lane >> 3, rr = lane & 7;
    const int a_ro = (grp & 1) * 8 + rr;   // row offset within 16
    const int a_ko = (grp >> 1) * 4;       // k offset within 8
    const int b_no = (grp >> 1) * 8 + rr;  // n offset within 16
    const int b_ko = (grp & 1) * 4;

#pragma unroll
    for (int ks = 0; ks < 8; ks++) {
        unsigned af[4][4];
        unsigned bf[4][2];
#pragma unroll
        for (int mt = 0; mt < 4; mt++) {
            const unsigned* p = &Qs[(wm * 64 + mt * 16 + a_ro) * 68 + ks * 8 + a_ko];
            ldsm_x4(af[mt], p);
        }
#pragma unroll
        for (int np = 0; np < 2; np++) {   // nt pairs (0,1),(2,3)
            unsigned q[4];
            const unsigned* p = &Ks[(wn * 32 + np * 16 + b_no) * 68 + ks * 8 + b_ko];
            ldsm_x4(q, p);
            bf[np * 2 + 0][0] = q[0]; bf[np * 2 + 0][1] = q[1];
            bf[np * 2 + 1][0] = q[2]; bf[np * 2 + 1][1] = q[3];
        }
#pragma unroll
        for (int mt = 0; mt < 4; mt++)
#pragma unroll
            for (int nt = 0; nt < 4; nt++)
                mma_tf32(acc[mt][nt], af[mt], bf[nt]);
    }
    __syncthreads();   // done with Qs/Ks; reuse as Cs

    // stage raw acc into Cs
#pragma unroll
    for (int mt = 0; mt < 4; mt++)
#pragma unroll
        for (int nt = 0; nt < 4; nt++)
#pragma unroll
            for (int i = 0; i < 4; i++) {
                int r = wm * 64 + mt * 16 + (lane >> 2) + ((i >= 2) ? 8 : 0);
                int c = wn * 32 + nt * 8 + (lane & 3) * 2 + (i & 1);
                Cs[r * 132 + c] = acc[mt][nt][i];
            }
    __syncthreads();

    // scan1: v = acc*0.125 + mask*(-1e9); write back to Cs; row max (2 thr/row)
    const int r  = tid >> 1;
    const int hh = tid & 1;
    float* rowp = Cs + r * 132 + hh * 64;
    const float* mrow = mask + (long long)(q0 + r) * SS + k0 + hh * 64;
    float mx = -INFINITY;
#pragma unroll
    for (int i = 0; i < 16; i++) {
        float4 c4 = *(const float4*)(rowp + i * 4);
        float4 m4 = *(const float4*)(mrow + i * 4);
        c4.x = fmaf(m4.x, -1e9f, c4.x * 0.125f);
        c4.y = fmaf(m4.y, -1e9f, c4.y * 0.125f);
        c4.z = fmaf(m4.z, -1e9f, c4.z * 0.125f);
        c4.w = fmaf(m4.w, -1e9f, c4.w * 0.125f);
        *(float4*)(rowp + i * 4) = c4;
        mx = fmaxf(mx, fmaxf(fmaxf(c4.x, c4.y), fmaxf(c4.z, c4.w)));
    }
    mx = fmaxf(mx, __shfl_xor_sync(0xffffffffu, mx, 1));

    // scan2: sumexp with row max
    float sum = 0.0f;
#pragma unroll
    for (int i = 0; i < 16; i++) {
        float4 c4 = *(const float4*)(rowp + i * 4);
        sum += __expf(c4.x - mx) + __expf(c4.y - mx)
             + __expf(c4.z - mx) + __expf(c4.w - mx);
    }
    sum += __shfl_xor_sync(0xffffffffu, sum, 1);
    if (hh == 0) {
        long long rowg = (long long)bh * SS + q0 + r;
        g_pm[rowg * NTILES + blockIdx.x] = mx;
        g_ps[rowg * NTILES + blockIdx.x] = sum;
    }
    __syncthreads();

    // scan3: coalesced tile write to gmem (raw masked logits)
    float* outp = attn + ((long long)bh * SS + q0) * SS + k0;
#pragma unroll
    for (int i = 0; i < 16; i++) {
        int idx = tid + i * 256;       // over 4096 float4
        int rr2 = idx >> 5;            // row (32 f4 per row)
        int cc4 = (idx & 31) * 4;
        float4 v = *(const float4*)(Cs + rr2 * 132 + cc4);
        *(float4*)(outp + (long long)rr2 * SS + cc4) = v;
    }
}

// ---------------------------------------------------------------------------
// K2: reduce partial stats -> per-row (max, 1/sum)
// ---------------------------------------------------------------------------
__global__ __launch_bounds__(256)
void stats_kernel()
{
    int row = blockIdx.x * 256 + threadIdx.x;
    if (row >= NROWS) return;
    const float* pm = g_pm + (long long)row * NTILES;
    const float* ps = g_ps + (long long)row * NTILES;
    float m = -INFINITY;
#pragma unroll
    for (int i = 0; i < NTILES; i++) m = fmaxf(m, pm[i]);
    float S = 0.0f;
#pragma unroll
    for (int i = 0; i < NTILES; i++) S += ps[i] * __expf(pm[i] - m);
    g_rm[row] = m;
    g_rs[row] = 1.0f / S;
}

// ---------------------------------------------------------------------------
// K3: normalize logits in place (-> attn output) and compute ctx = attn @ V.
// Grid: (16 q-blocks, 64 bh). 128 rows x 64 cols out, k chunks of 64.
// ---------------------------------------------------------------------------
__global__ __launch_bounds__(256)
void ctx_fused_kernel(float* __restrict__ attn)
{
    extern __shared__ unsigned dynsm[];
    unsigned* Ps = dynsm;              // [m][k] stride 68
    unsigned* Vs = dynsm + 128 * 68;   // [n][k] stride 68
    float* sm_m    = (float*)(dynsm + 128 * 68 + 64 * 68);
    float* sm_rinv = sm_m + 128;

    const int tid  = threadIdx.x;
    const int lane = tid & 31;
    const int warp = tid >> 5;
    const int wm = warp >> 1;          // 0..3  (WM=32)
    const int wn = warp & 1;           // 0..1  (WN=32)
    const int bh = blockIdx.y;
    const int b  = bh / HH;
    const int h  = bh % HH;
    const int q0 = blockIdx.x * 128;

    // preload row stats
    if (tid < 128) {
        long long rowg = (long long)bh * SS + q0 + tid;
        sm_m[tid]    = g_rm[rowg];
        sm_rinv[tid] = g_rs[rowg];
    }
    __syncthreads();

    float* Ab = attn + ((long long)bh * SS + q0) * SS;
    const float* Vb = g_Vh + (long long)bh * SS * DP;

    float acc[2][4][4];
#pragma unroll
    for (int mt = 0; mt < 2; mt++)
#pragma unroll
        for (int nt = 0; nt < 4; nt++)
#pragma unroll
            for (int i = 0; i < 4; i++) acc[mt][nt][i] = 0.0f;

    const int grp = lane >> 3, rr = lane & 7;
    const int a_ro = (grp & 1) * 8 + rr;
    const int a_ko = (grp >> 1) * 4;
    const int b_no = (grp >> 1) * 8 + rr;
    const int b_ko = (grp & 1) * 4;

    for (int k0 = 0; k0 < SS; k0 += 64) {
        // load logits chunk 128x64, normalize, write attn, stage tf32
#pragma unroll
        for (int i = 0; i < 8; i++) {
            int idx = tid + i * 256;   // 0..2047 f4
            int r   = idx >> 4;
            int c4  = (idx & 15) * 4;
            float* gp = Ab + (long long)r * SS + k0 + c4;
            float4 v = *(const float4*)gp;
            float m = sm_m[r], rv = sm_rinv[r];
            v.x = __expf(v.x - m) * rv;
            v.y = __expf(v.y - m) * rv;
            v.z = __expf(v.z - m) * rv;
            v.w = __expf(v.w - m) * rv;
            *(float4*)gp = v;          // normalized attn (in place)
            Ps[r * 68 + c4 + 0] = f2tf(v.x);
            Ps[r * 68 + c4 + 1] = f2tf(v.y);
            Ps[r * 68 + c4 + 2] = f2tf(v.z);
            Ps[r * 68 + c4 + 3] = f2tf(v.w);
        }
        // load V chunk [64 k x 64 n] -> Vs[n][k]
#pragma unroll
        for (int i = 0; i < 4; i++) {
            int idx = tid + i * 256;   // 0..1023 f4
            int kk  = idx >> 4;
            int n4  = (idx & 15) * 4;
            float4 v = *(const float4*)(Vb + (long long)(k0 + kk) * DP + n4);
            Vs[(n4 + 0) * 68 + kk] = f2tf(v.x);
            Vs[(n4 + 1) * 68 + kk] = f2tf(v.y);
            Vs[(n4 + 2) * 68 + kk] = f2tf(v.z);
            Vs[(n4 + 3) * 68 + kk] = f2tf(v.w);
        }
        __syncthreads();

#pragma unroll
        for (int ks = 0; ks < 8; ks++) {
            unsigned af[2][4];
            unsigned bf[4][2];
#pragma unroll
            for (int mt = 0; mt < 2; mt++) {
                const unsigned* p = &Ps[(wm * 32 + mt * 16 + a_ro) * 68 + ks * 8 + a_ko];
                ldsm_x4(af[mt], p);
            }
#pragma unroll
            for (int np = 0; np < 2; np++) {
                unsigned q[4];
                const unsigned* p = &Vs[(wn * 32 + np * 16 + b_no) * 68 + ks * 8 + b_ko];
                ldsm_x4(q, p);
                bf[np * 2 + 0][0] = q[0]; bf[np * 2 + 0][1] = q[1];
                bf[np * 2 + 1][0] = q[2]; bf[np * 2 + 1][1] = q[3];
            }
#pragma unroll
            for (int mt = 0; mt < 2; mt++)
#pragma unroll
                for (int nt = 0; nt < 4; nt++)
                    mma_tf32(acc[mt][nt], af[mt], bf[nt]);
        }
        __syncthreads();
    }

    // write ctx merged [b,s,D]
#pragma unroll
    for (int mt = 0; mt < 2; mt++)
#pragma unroll
        for (int nt = 0; nt < 4; nt++)
#pragma unroll
            for (int i = 0; i < 4; i++) {
                int s = q0 + wm * 32 + mt * 16 + (lane >> 2) + ((i >= 2) ? 8 : 0);
                int d = wn * 32 + nt * 8 + (lane & 3) * 2 + (i & 1);
                g_ctx[((long long)b * SS + s) * DD + h * DP + d] = acc[mt][nt][i];
            }
}

// ---------------------------------------------------------------------------
extern "C" void kernel_launch(void* const* d_in, const int* in_sizes, int n_in,
                              void* d_out, int out_size)
{
    const float* q    = (const float*)d_in[0];
    const float* k    = (const float*)d_in[1];
    const float* v    = (const float*)d_in[2];
    const float* mask = (const float*)d_in[3];
    const float* Wq   = (const float*)d_in[4];
    const float* bq   = (const float*)d_in[5];
    const float* Wk   = (const float*)d_in[6];
    const float* bk   = (const float*)d_in[7];
    const float* Wv   = (const float*)d_in[8];
    const float* bv   = (const float*)d_in[9];
    const float* Wo   = (const float*)d_in[10];
    const float* bo   = (const float*)d_in[11];

    float* outp  = (float*)d_out;
    float* attnp = nullptr;
    if ((long long)out_size >= OUT_ELEMS + ATTN_ELEMS) {
        attnp = outp + OUT_ELEMS;
    } else {
        void* sym = nullptr;
        cudaGetSymbolAddress(&sym, g_attn);
        attnp = (float*)sym;
    }

    float* Qh = nullptr;  cudaGetSymbolAddress((void**)&Qh,  g_Qh);
    float* Kh = nullptr;  cudaGetSymbolAddress((void**)&Kh,  g_Kh);
    float* Vh = nullptr;  cudaGetSymbolAddress((void**)&Vh,  g_Vh);
    float* ctx = nullptr; cudaGetSymbolAddress((void**)&ctx, g_ctx);

    // --- Q/K/V projections (head-split) ---
    mma_gemm_kernel<128,128,16,64,32,1><<<dim3(8,64,1), 256>>>(
        q, Wq, bq, Qh, MM, DD, DD, 1.0f);
    mma_gemm_kernel<128,128,16,64,32,1><<<dim3(8,64,1), 256>>>(
        k, Wk, bk, Kh, MM, DD, DD, 1.0f);
    mma_gemm_kernel<128,128,16,64,32,1><<<dim3(8,64,1), 256>>>(
        v, Wv, bv, Vh, MM, DD, DD, 1.0f);

    // --- K1: QK^T + mask + scale + partial stats ---
    {
        int smem = 2 * 128 * 68 * 4;   // 69,632 (>= Cs 128*132*4)
        cudaFuncSetAttribute(qk_kernel,
            cudaFuncAttributeMaxDynamicSharedMemorySize, smem);
        qk_kernel<<<dim3(16,16,BB*HH), 256, smem>>>(mask, attnp);
    }

    // --- K2: finalize row stats ---
    stats_kernel<<<(NROWS + 255)/256, 256>>>();

    // --- K3: normalize attn in place + ctx = attn @ V ---
    {
        int smem = (128*68 + 64*68) * 4 + 2 * 128 * 4;  // 53,248
        cudaFuncSetAttribute(ctx_fused_kernel,
            cudaFuncAttributeMaxDynamicSharedMemorySize, smem);
        ctx_fused_kernel<<<dim3(16, BB*HH), 256, smem>>>(attnp);
    }

    // --- output projection ---
    mma_gemm_kernel<128,128,16,64,32,0><<<dim3(8,64,1), 256>>>(
        ctx, Wo, bo, outp, MM, DD, DD, 1.0f);
}

// round 6
// speedup vs baseline: 1.2823x; 1.2823x over previous
#include <cuda_runtime.h>
#include <cuda_bf16.h>
#include <math.h>

#define BB 4
#define SS 2048
#define DD 1024
#define HH 16
#define DP 64
#define MM (BB*SS)

static const long long OUT_ELEMS  = (long long)BB*SS*DD;
static const long long ATTN_ELEMS = (long long)BB*HH*(long long)SS*SS;

// Scratch (__device__ globals per allocation rules)
__device__ float g_Qh[BB*HH*SS*DP];
__device__ float g_Kh[BB*HH*SS*DP];
__device__ float g_Vh[BB*HH*SS*DP];
__device__ float g_ctx[BB*SS*DD];
__device__ float g_attn[BB*HH*(long long)SS*SS];

// ---------------------------------------------------------------------------
__device__ __forceinline__ unsigned f2tf(float x) {
    unsigned r;
    asm("cvt.rna.tf32.f32 %0, %1;" : "=r"(r) : "f"(x));
    return r;
}

__device__ __forceinline__ void mma_tf32(float c[4], const unsigned a[4], const unsigned b[2]) {
    asm volatile(
        "mma.sync.aligned.m16n8k8.row.col.f32.tf32.tf32.f32 "
        "{%0,%1,%2,%3}, {%4,%5,%6,%7}, {%8,%9}, {%0,%1,%2,%3};"
        : "+f"(c[0]), "+f"(c[1]), "+f"(c[2]), "+f"(c[3])
        : "r"(a[0]), "r"(a[1]), "r"(a[2]), "r"(a[3]), "r"(b[0]), "r"(b[1]));
}

// ldmatrix x4 (b16 view) — verified in R5 to produce correct tf32 fragments.
__device__ __forceinline__ void ldsm_x4(unsigned r[4], const unsigned* p) {
    unsigned addr = (unsigned)__cvta_generic_to_shared(p);
    asm volatile("ldmatrix.sync.aligned.m8n8.x4.shared.b16 {%0,%1,%2,%3}, [%4];"
                 : "=r"(r[0]), "=r"(r[1]), "=r"(r[2]), "=r"(r[3]) : "r"(addr));
}

// ---------------------------------------------------------------------------
// Generic TF32 tensor-core GEMM:  C = alpha * A @ op(B) + bias
//  BT=false: B is [K,N] row-major.  BT=true: B is [N,K] row-major (B^T used).
//  SPLIT: 0 = C[z*sC + r*N+c]; 1 = head-split store [b,h,s,d];
//         2 = merge store ctx layout [b,s,D] from per-(b,h) rows.
// A-fragments via ldmatrix.x4 (R6 change); B-fragments scalar LDS (unchanged).
// ---------------------------------------------------------------------------
template<int BM, int BN, int BK, int WM, int WN, bool BT, int SPLIT>
__global__ __launch_bounds__(256)
void mma_gemm_kernel(const float* __restrict__ A,
                     const float* __restrict__ Bm,
                     const float* __restrict__ bias,
                     float* __restrict__ C,
                     int M, int N, int K,
                     long long sA, long long sB, long long sC,
                     float alpha)
{
    constexpr int AP = BK + 4;
    constexpr int BP = BN + 4;
    __shared__ unsigned As[BM * AP];
    __shared__ unsigned Bs[BK * BP];

    const int tid  = threadIdx.x;
    const int lane = tid & 31;
    const int warp = tid >> 5;
    constexpr int WN_CNT = BN / WN;
    const int wm = warp / WN_CNT;
    const int wn = warp % WN_CNT;
    const int row0 = blockIdx.y * BM;
    const int col0 = blockIdx.x * BN;
    const int z    = blockIdx.z;

    A  += (long long)z * sA;
    Bm += (long long)z * sB;

    constexpr int MT = WM / 16;
    constexpr int NT = WN / 8;
    float cfr[MT][NT][4];
#pragma unroll
    for (int mt = 0; mt < MT; mt++)
#pragma unroll
        for (int nt = 0; nt < NT; nt++)
#pragma unroll
            for (int i = 0; i < 4; i++) cfr[mt][nt][i] = 0.0f;

    // ldmatrix address decomposition for the A fragment (verified in R5):
    // lanes 0-7 -> rows +0..7 @k+0 ; 8-15 -> rows +8..15 @k+0 ;
    // 16-23 -> rows +0..7 @k+4 ; 24-31 -> rows +8..15 @k+4
    const int grp  = lane >> 3, rrw = lane & 7;
    const int a_ro = (grp & 1) * 8 + rrw;
    const int a_ko = (grp >> 1) * 4;

    for (int k0 = 0; k0 < K; k0 += BK) {
        // ---- load A tile [BM x BK] as tf32, layout As[m][k]
#pragma unroll
        for (int i = 0; i < (BM * BK / 4) / 256; i++) {
            int idx = tid + i * 256;
            int r   = idx / (BK / 4);
            int kq  = (idx % (BK / 4)) * 4;
            float4 v = *(const float4*)(A + (long long)(row0 + r) * K + k0 + kq);
            As[r * AP + kq + 0] = f2tf(v.x);
            As[r * AP + kq + 1] = f2tf(v.y);
            As[r * AP + kq + 2] = f2tf(v.z);
            As[r * AP + kq + 3] = f2tf(v.w);
        }
        // ---- load B tile [BK x BN], layout Bs[k][n]
        if (BT) {
#pragma unroll
            for (int i = 0; i < (BN * BK / 4) / 256; i++) {
                int idx = tid + i * 256;
                int n   = idx / (BK / 4);
                int kq  = (idx % (BK / 4)) * 4;
                float4 v = *(const float4*)(Bm + (long long)(col0 + n) * K + k0 + kq);
                Bs[(kq + 0) * BP + n] = f2tf(v.x);
                Bs[(kq + 1) * BP + n] = f2tf(v.y);
                Bs[(kq + 2) * BP + n] = f2tf(v.z);
                Bs[(kq + 3) * BP + n] = f2tf(v.w);
            }
        } else {
#pragma unroll
            for (int i = 0; i < (BK * BN / 4) / 256; i++) {
                int idx = tid + i * 256;
                int kk  = idx / (BN / 4);
                int nq  = (idx % (BN / 4)) * 4;
                float4 v = *(const float4*)(Bm + (long long)(k0 + kk) * N + col0 + nq);
                Bs[kk * BP + nq + 0] = f2tf(v.x);
                Bs[kk * BP + nq + 1] = f2tf(v.y);
                Bs[kk * BP + nq + 2] = f2tf(v.z);
                Bs[kk * BP + nq + 3] = f2tf(v.w);
            }
        }
        __syncthreads();

#pragma unroll
        for (int ks = 0; ks < BK / 8; ks++) {
            unsigned af[MT][4];
            unsigned bf[NT][2];
            const int kb = ks * 8 + (lane & 3);
#pragma unroll
            for (int mt = 0; mt < MT; mt++) {
                const unsigned* p = &As[(wm * WM + mt * 16 + a_ro) * AP + ks * 8 + a_ko];
                ldsm_x4(af[mt], p);
            }
#pragma unroll
            for (int nt = 0; nt < NT; nt++) {
                int cc = wn * WN + nt * 8 + (lane >> 2);
                bf[nt][0] = Bs[kb * BP + cc];
                bf[nt][1] = Bs[(kb + 4) * BP + cc];
            }
#pragma unroll
            for (int mt = 0; mt < MT; mt++)
#pragma unroll
                for (int nt = 0; nt < NT; nt++)
                    mma_tf32(cfr[mt][nt], af[mt], bf[nt]);
        }
        __syncthreads();
    }

    // ---- epilogue
#pragma unroll
    for (int mt = 0; mt < MT; mt++) {
#pragma unroll
        for (int nt = 0; nt < NT; nt++) {
#pragma unroll
            for (int i = 0; i < 4; i++) {
                int r = row0 + wm * WM + mt * 16 + (lane >> 2) + ((i >= 2) ? 8 : 0);
                int c = col0 + wn * WN + nt * 8 + (lane & 3) * 2 + (i & 1);
                float v = cfr[mt][nt][i] * alpha + (bias ? bias[c] : 0.0f);
                if (SPLIT == 0) {
                    C[(long long)z * sC + (long long)r * N + c] = v;
                } else if (SPLIT == 1) {
                    int b = r / SS, s = r % SS;
                    int h = c / DP, d = c % DP;
                    C[(((long long)b * HH + h) * SS + s) * DP + d] = v;
                } else { // SPLIT == 2 : merge ctx
                    int b = z / HH, h = z % HH;
                    C[((long long)b * SS + r) * DD + h * DP + c] = v;
                }
            }
        }
    }
}

// ---------------------------------------------------------------------------
// In-place row softmax over attn buffer: one 128-thread block per row.
// Row = 2048 floats, held in registers (16 per thread).
// ---------------------------------------------------------------------------
__global__ __launch_bounds__(128)
void softmax_kernel(float* __restrict__ attn, const float* __restrict__ mask)
{
    const long long row = blockIdx.x;
    const int q = (int)(row % SS);
    float* p = attn + row * SS;
    const float* m = mask + (long long)q * SS;
    const int t = threadIdx.x;

    float4 vals[4];
    float mx = -INFINITY;
#pragma unroll
    for (int i = 0; i < 4; i++) {
        float4 lv = ((const float4*)p)[t + i * 128];
        float4 mv = ((const float4*)m)[t + i * 128];
        lv.x = fmaf(mv.x, -1e9f, lv.x);
        lv.y = fmaf(mv.y, -1e9f, lv.y);
        lv.z = fmaf(mv.z, -1e9f, lv.z);
        lv.w = fmaf(mv.w, -1e9f, lv.w);
        vals[i] = lv;
        mx = fmaxf(mx, fmaxf(fmaxf(lv.x, lv.y), fmaxf(lv.z, lv.w)));
    }

    __shared__ float red[4];
#pragma unroll
    for (int o = 16; o > 0; o >>= 1)
        mx = fmaxf(mx, __shfl_xor_sync(0xffffffffu, mx, o));
    if ((t & 31) == 0) red[t >> 5] = mx;
    __syncthreads();
    mx = fmaxf(fmaxf(red[0], red[1]), fmaxf(red[2], red[3]));
    __syncthreads();

    float ssum = 0.0f;
#pragma unroll
    for (int i = 0; i < 4; i++) {
        vals[i].x = __expf(vals[i].x - mx);
        vals[i].y = __expf(vals[i].y - mx);
        vals[i].z = __expf(vals[i].z - mx);
        vals[i].w = __expf(vals[i].w - mx);
        ssum += vals[i].x + vals[i].y + vals[i].z + vals[i].w;
    }
#pragma unroll
    for (int o = 16; o > 0; o >>= 1)
        ssum += __shfl_xor_sync(0xffffffffu, ssum, o);
    if ((t & 31) == 0) red[t >> 5] = ssum;
    __syncthreads();
    ssum = red[0] + red[1] + red[2] + red[3];
    const float rinv = 1.0f / ssum;

#pragma unroll
    for (int i = 0; i < 4; i++) {
        float4 v = vals[i];
        v.x *= rinv; v.y *= rinv; v.z *= rinv; v.w *= rinv;
        ((float4*)p)[t + i * 128] = v;
    }
}

// ---------------------------------------------------------------------------
extern "C" void kernel_launch(void* const* d_in, const int* in_sizes, int n_in,
                              void* d_out, int out_size)
{
    const float* q    = (const float*)d_in[0];
    const float* k    = (const float*)d_in[1];
    const float* v    = (const float*)d_in[2];
    const float* mask = (const float*)d_in[3];
    const float* Wq   = (const float*)d_in[4];
    const float* bq   = (const float*)d_in[5];
    const float* Wk   = (const float*)d_in[6];
    const float* bk   = (const float*)d_in[7];
    const float* Wv   = (const float*)d_in[8];
    const float* bv   = (const float*)d_in[9];
    const float* Wo   = (const float*)d_in[10];
    const float* bo   = (const float*)d_in[11];

    float* outp  = (float*)d_out;
    float* attnp = nullptr;
    if ((long long)out_size >= OUT_ELEMS + ATTN_ELEMS) {
        attnp = outp + OUT_ELEMS;
    } else {
        void* sym = nullptr;
        cudaGetSymbolAddress(&sym, g_attn);
        attnp = (float*)sym;
    }

    float* Qh = nullptr;  cudaGetSymbolAddress((void**)&Qh,  g_Qh);
    float* Kh = nullptr;  cudaGetSymbolAddress((void**)&Kh,  g_Kh);
    float* Vh = nullptr;  cudaGetSymbolAddress((void**)&Vh,  g_Vh);
    float* ctx = nullptr; cudaGetSymbolAddress((void**)&ctx, g_ctx);

    // --- Q/K/V projections (head-split outputs) ---
    mma_gemm_kernel<128,128,16,64,32,false,1><<<dim3(8,64,1), 256>>>(
        q, Wq, bq, Qh, MM, DD, DD, 0, 0, 0, 1.0f);
    mma_gemm_kernel<128,128,16,64,32,false,1><<<dim3(8,64,1), 256>>>(
        k, Wk, bk, Kh, MM, DD, DD, 0, 0, 0, 1.0f);
    mma_gemm_kernel<128,128,16,64,32,false,1><<<dim3(8,64,1), 256>>>(
        v, Wv, bv, Vh, MM, DD, DD, 0, 0, 0, 1.0f);

    // --- logits = (Q @ K^T) / 8, batched over 64 (b,h) ---
    mma_gemm_kernel<128,128,16,64,32,true,0><<<dim3(16,16,BB*HH), 256>>>(
        Qh, Kh, nullptr, attnp, SS, SS, DP,
        (long long)SS*DP, (long long)SS*DP, (long long)SS*SS, 0.125f);

    // --- softmax in place (with mask) ---
    softmax_kernel<<<BB*HH*SS, 128>>>(attnp, mask);

    // --- ctx = attn @ V, merged layout ---
    mma_gemm_kernel<128,64,16,32,32,false,2><<<dim3(1,16,BB*HH), 256>>>(
        attnp, Vh, nullptr, ctx, SS, DP, SS,
        (long long)SS*SS, (long long)SS*DP, 0, 1.0f);

    // --- output projection ---
    mma_gemm_kernel<128,128,16,64,32,false,0><<<dim3(8,64,1), 256>>>(
        ctx, Wo, bo, outp, MM, DD, DD, 0, 0, 0, 1.0f);
}